// round 15
// baseline (speedup 1.0000x reference)
#include <cuda_runtime.h>
#include <cuda_fp16.h>
#include <cstdint>

#define BATCH 32
#define CCH   512
#define RCH   256
#define HWSZ  1024

// Scratch (device globals). GEMM operands fp16 k-minor; E fp32; P fp16.
__device__ __half g_xTh   [BATCH * HWSZ * CCH];            // 32 MB [b][n][c]
__device__ __half g_Wh    [(RCH + RCH + CCH) * CCH];       // 1 MB  Wk|Wp|Wv
__device__ __half g_fkeyTh[BATCH * HWSZ * RCH];            // 16 MB [b][n][r]
__device__ __half g_fprodTh[BATCH * HWSZ * RCH];           // 16 MB [b][m][r]
__device__ __half g_fvalh [BATCH * CCH * HWSZ];            // 32 MB [b][c][m]
__device__ float  g_energy[(size_t)BATCH * HWSZ * HWSZ];   // 128 MB E fp32
__device__ __half g_Ph    [(size_t)BATCH * HWSZ * HWSZ];   // 64 MB P = exp(s-max)
__device__ float  g_inv   [BATCH * HWSZ];                  // 1/rowsum

// ---------------------------------------------------------------------------
// PTX helpers
// ---------------------------------------------------------------------------
__device__ __forceinline__ uint32_t s2u(const void* p) {
    uint32_t a;
    asm("{ .reg .u64 t; cvta.to.shared.u64 t, %1; cvt.u32.u64 %0, t; }" : "=r"(a) : "l"(p));
    return a;
}
__device__ __forceinline__ void cp_async16(uint32_t dst, const void* src) {
    asm volatile("cp.async.cg.shared.global [%0], [%1], 16;" :: "r"(dst), "l"(src));
}
#define CP_COMMIT() asm volatile("cp.async.commit_group;" ::: "memory")
#define CP_WAIT1()  asm volatile("cp.async.wait_group 1;" ::: "memory")
#define CP_WAIT0()  asm volatile("cp.async.wait_group 0;" ::: "memory")

__device__ __forceinline__ void mma_f16(float c[4], const uint32_t a[4], const uint32_t b[2]) {
    asm volatile(
        "mma.sync.aligned.m16n8k16.row.col.f32.f16.f16.f32 "
        "{%0,%1,%2,%3}, {%4,%5,%6,%7}, {%8,%9}, {%0,%1,%2,%3};"
        : "+f"(c[0]), "+f"(c[1]), "+f"(c[2]), "+f"(c[3])
        : "r"(a[0]), "r"(a[1]), "r"(a[2]), "r"(a[3]), "r"(b[0]), "r"(b[1]));
}

__device__ __forceinline__ void ldsm4(uint32_t* r, uint32_t addr) {
    asm volatile("ldmatrix.sync.aligned.m8n8.x4.shared.b16 {%0,%1,%2,%3}, [%4];"
        : "=r"(r[0]), "=r"(r[1]), "=r"(r[2]), "=r"(r[3]) : "r"(addr));
}

// ---------------------------------------------------------------------------
// GEMM core: D[128x64]fp32 = A[128xK]h * B[64xK]h^T, operands k-minor fp16.
// BK=64 halves (128B rows). 2-stage cp.async pipeline. 8 warps as 4(m)x2(n),
// warp tile 32x32, acc 32 regs -> 3 CTAs/SM (24 warps) via launch_bounds.
// ---------------------------------------------------------------------------
#define A_BYTES 16384                     // 128 rows x 128B
#define B_BYTES 8192                      // 64 rows x 128B
#define STAGE_BYTES (A_BYTES + B_BYTES)   // 24 KB

extern __shared__ uint32_t smp[];         // [2][STAGE_BYTES] = 48 KB

__device__ __forceinline__ void stage_tileA(uint32_t sbase, const __half* src,
                                            size_t ld, int tid)
{
    #pragma unroll
    for (int v = 0; v < 4; v++) {
        const int idx = tid + v * 256;                   // 0..1023 -> 128 rows
        const int row = idx >> 3;
        const int cg  = idx & 7;
        const uint32_t col4 = (cg * 4) ^ ((row & 7) * 4);
        cp_async16(sbase + (row * 32 + col4) * 4, src + (size_t)row * ld + cg * 8);
    }
}
__device__ __forceinline__ void stage_tileB(uint32_t sbase, const __half* src,
                                            size_t ld, int tid)
{
    #pragma unroll
    for (int v = 0; v < 2; v++) {
        const int idx = tid + v * 256;                   // 0..511 -> 64 rows
        const int row = idx >> 3;
        const int cg  = idx & 7;
        const uint32_t col4 = (cg * 4) ^ ((row & 7) * 4);
        cp_async16(sbase + (row * 32 + col4) * 4, src + (size_t)row * ld + cg * 8);
    }
}

struct FragAddr {
    uint32_t afull[2], aK0[2];
    uint32_t bfull[2], bK0[2];
};

__device__ __forceinline__ FragAddr make_frag_addr(int lane, int wm, int wn)
{
    FragAddr f;
    const int rowoff = ((lane >> 3) & 1) * 8 + (lane & 7);
    const int c4a = ((lane >> 4) & 1) * 4;
    #pragma unroll
    for (int mi = 0; mi < 2; mi++) {
        const int arow = wm + mi * 16 + rowoff;
        f.afull[mi] = (uint32_t)arow * 128;
        f.aK0[mi]   = (uint32_t)(c4a ^ (4 * (arow & 7)));
    }
    const int c4b = ((lane >> 3) & 1) * 4;
    #pragma unroll
    for (int p = 0; p < 2; p++) {
        const int brow = wn + (2 * p + ((lane >> 4) & 1)) * 8 + (lane & 7);
        f.bfull[p] = (uint32_t)brow * 128;
        f.bK0[p]   = (uint32_t)(c4b ^ (4 * (brow & 7)));
    }
    return f;
}

__device__ __forceinline__ void mma_chunk(uint32_t abase, uint32_t bbase,
                                          const FragAddr& f, float acc[2][4][4])
{
    #pragma unroll
    for (int kk = 0; kk < 4; kk++) {                 // 4 k16-steps per BK=64
        const uint32_t k = kk * 8;
        uint32_t a[2][4], b[2][4];
        #pragma unroll
        for (int mi = 0; mi < 2; mi++)
            ldsm4(a[mi], abase + f.afull[mi] + ((k ^ f.aK0[mi]) << 2));
        #pragma unroll
        for (int p = 0; p < 2; p++)
            ldsm4(b[p], bbase + f.bfull[p] + ((k ^ f.bK0[p]) << 2));
        #pragma unroll
        for (int mi = 0; mi < 2; mi++)
            #pragma unroll
            for (int ni = 0; ni < 4; ni++)
                mma_f16(acc[mi][ni], a[mi], &b[ni >> 1][(ni & 1) * 2]);
    }
}

__device__ __forceinline__ void gemm_tn(const __half* __restrict__ A, size_t lda,
                                        const __half* __restrict__ B, size_t ldb,
                                        int nIter, float acc[2][4][4],
                                        int wm, int wn)
{
    const int tid = threadIdx.x;
    const uint32_t sm0 = s2u(smp);
    const FragAddr f = make_frag_addr(tid & 31, wm, wn);

    stage_tileA(sm0, A, lda, tid);
    stage_tileB(sm0 + A_BYTES, B, ldb, tid);
    CP_COMMIT();

    for (int it = 0; it < nIter; ++it) {
        if (it + 1 < nIter) {
            const uint32_t sb = sm0 + ((it + 1) & 1) * STAGE_BYTES;
            stage_tileA(sb, A + (size_t)(it + 1) * 64, lda, tid);
            stage_tileB(sb + A_BYTES, B + (size_t)(it + 1) * 64, ldb, tid);
            CP_COMMIT();
            CP_WAIT1();
        } else {
            CP_WAIT0();
        }
        __syncthreads();
        const uint32_t abase = sm0 + (it & 1) * STAGE_BYTES;
        mma_chunk(abase, abase + A_BYTES, f, acc);
        __syncthreads();
    }
}

// ---------------------------------------------------------------------------
// W -> half converter (Wk | Wp | Wv packed into g_Wh)
// ---------------------------------------------------------------------------
__global__ __launch_bounds__(256)
void wconv_kernel(const float* __restrict__ Wk, const float* __restrict__ Wp,
                  const float* __restrict__ Wv)
{
    const int i = blockIdx.x * 256 + threadIdx.x;
    float v;
    if (i < RCH * CCH)          v = Wk[i];
    else if (i < 2 * RCH * CCH) v = Wp[i - RCH * CCH];
    else                        v = Wv[i - 2 * RCH * CCH];
    g_Wh[i] = __float2half(v);
}

// ---------------------------------------------------------------------------
// Transpose + convert: xTh[b][n][c] = half(x[b][c][n])
// ---------------------------------------------------------------------------
__global__ __launch_bounds__(256)
void transpose_kernel(const float* __restrict__ x)
{
    __shared__ float t[32][33];
    const int b  = blockIdx.z;
    const int n0 = blockIdx.x * 32;
    const int c0 = blockIdx.y * 32;
    const int tx = threadIdx.x & 31;
    const int ty = threadIdx.x >> 5;

    const float* xb = x + (size_t)b * CCH * HWSZ;
    #pragma unroll
    for (int i = 0; i < 4; i++)
        t[ty + i * 8][tx] = xb[(size_t)(c0 + ty + i * 8) * HWSZ + n0 + tx];
    __syncthreads();
    __half* xT = g_xTh + (size_t)b * HWSZ * CCH;
    #pragma unroll
    for (int i = 0; i < 4; i++)
        xT[(size_t)(n0 + ty + i * 8) * CCH + c0 + tx] = __float2half(t[tx][ty + i * 8]);
}

// ---------------------------------------------------------------------------
// proj_kp (merged k+p): D[n][r] = sum_c xTh[n][c] * Wh[r][c] + bias[r] -> half
// blockIdx.y in [0,8): y>>2 selects proj, (y&3)*64 = r-tile.
// ---------------------------------------------------------------------------
__global__ __launch_bounds__(256, 3)
void proj_kp_kernel(const float* __restrict__ bk, const float* __restrict__ bp)
{
    const int b  = blockIdx.z;
    const int n0 = blockIdx.x * 128;
    const int which = blockIdx.y >> 2;
    const int r0 = (blockIdx.y & 3) * 64;
    const __half* W    = g_Wh + which * (RCH * CCH);
    const float*  bias = which ? bp : bk;
    __half* dst        = which ? g_fprodTh : g_fkeyTh;

    const int tid = threadIdx.x;
    const int wid = tid >> 5, lane = tid & 31;
    const int wm = (wid >> 1) * 32, wn = (wid & 1) * 32;
    const int g = lane >> 2, tig = lane & 3;

    float acc[2][4][4] = {};
    gemm_tn(g_xTh + (size_t)b * HWSZ * CCH + (size_t)n0 * CCH, CCH,
            W + (size_t)r0 * CCH, CCH, CCH / 64, acc, wm, wn);

    #pragma unroll
    for (int ni = 0; ni < 4; ni++) {
        const int col = r0 + wn + ni * 8 + tig * 2;
        const float2 bv = *reinterpret_cast<const float2*>(&bias[col]);
        #pragma unroll
        for (int mi = 0; mi < 2; mi++) {
            const int row = n0 + wm + mi * 16 + g;
            *reinterpret_cast<__half2*>(&dst[((size_t)b * HWSZ + row) * RCH + col]) =
                __floats2half2_rn(acc[mi][ni][0] + bv.x, acc[mi][ni][1] + bv.y);
            *reinterpret_cast<__half2*>(&dst[((size_t)b * HWSZ + row + 8) * RCH + col]) =
                __floats2half2_rn(acc[mi][ni][2] + bv.x, acc[mi][ni][3] + bv.y);
        }
    }
}

// ---------------------------------------------------------------------------
// proj_v: D[c][m] = sum_ci Wvh[c][ci] * xTh[m][ci] + bias[c] -> fvalh[b][c][m]
// ---------------------------------------------------------------------------
__global__ __launch_bounds__(256, 3)
void proj_v_kernel(const float* __restrict__ bias)
{
    const int b  = blockIdx.z;
    const int c0 = blockIdx.x * 128;
    const int m0 = blockIdx.y * 64;
    const int tid = threadIdx.x;
    const int wid = tid >> 5, lane = tid & 31;
    const int wm = (wid >> 1) * 32, wn = (wid & 1) * 32;
    const int g = lane >> 2, tig = lane & 3;

    float acc[2][4][4] = {};
    gemm_tn(g_Wh + 2 * (RCH * CCH) + (size_t)c0 * CCH, CCH,
            g_xTh + (size_t)b * HWSZ * CCH + (size_t)m0 * CCH, CCH,
            CCH / 64, acc, wm, wn);

    #pragma unroll
    for (int mi = 0; mi < 2; mi++) {
        const int row = c0 + wm + mi * 16 + g;
        const float b0 = bias[row], b1 = bias[row + 8];
        #pragma unroll
        for (int ni = 0; ni < 4; ni++) {
            const int col = m0 + wn + ni * 8 + tig * 2;
            *reinterpret_cast<__half2*>(&g_fvalh[((size_t)b * CCH + row) * HWSZ + col]) =
                __floats2half2_rn(acc[mi][ni][0] + b0, acc[mi][ni][1] + b0);
            *reinterpret_cast<__half2*>(&g_fvalh[((size_t)b * CCH + row + 8) * HWSZ + col]) =
                __floats2half2_rn(acc[mi][ni][2] + b1, acc[mi][ni][3] + b1);
        }
    }
}

// ---------------------------------------------------------------------------
// energy: E[n][m] fp32 = sum_r fkeyTh[n][r] * fprodTh[m][r]
// ---------------------------------------------------------------------------
__global__ __launch_bounds__(256, 3)
void energy_kernel()
{
    const int b  = blockIdx.z;
    const int m0 = blockIdx.x * 64;
    const int n0 = blockIdx.y * 128;
    const int tid = threadIdx.x;
    const int wid = tid >> 5, lane = tid & 31;
    const int wm = (wid >> 1) * 32, wn = (wid & 1) * 32;
    const int g = lane >> 2, tig = lane & 3;

    float acc[2][4][4] = {};
    gemm_tn(g_fkeyTh  + ((size_t)b * HWSZ + n0) * RCH, RCH,
            g_fprodTh + ((size_t)b * HWSZ + m0) * RCH, RCH,
            RCH / 64, acc, wm, wn);

    float* Eb = g_energy + (size_t)b * HWSZ * HWSZ;
    #pragma unroll
    for (int mi = 0; mi < 2; mi++) {
        const int row = n0 + wm + mi * 16 + g;
        #pragma unroll
        for (int ni = 0; ni < 4; ni++) {
            const int col = m0 + wn + ni * 8 + tig * 2;
            *reinterpret_cast<float2*>(&Eb[(size_t)row * HWSZ + col]) =
                make_float2(acc[mi][ni][0], acc[mi][ni][1]);
            *reinterpret_cast<float2*>(&Eb[(size_t)(row + 8) * HWSZ + col]) =
                make_float2(acc[mi][ni][2], acc[mi][ni][3]);
        }
    }
}

// ---------------------------------------------------------------------------
// softmax: per row, P = half(exp(s - rowmax)), g_inv = 1/sum.
// ---------------------------------------------------------------------------
__device__ __forceinline__ float block_reduce(float v, bool do_max)
{
    __shared__ float red[8];
    #pragma unroll
    for (int o = 16; o > 0; o >>= 1) {
        const float other = __shfl_xor_sync(0xffffffffu, v, o);
        v = do_max ? fmaxf(v, other) : (v + other);
    }
    const int wid = threadIdx.x >> 5;
    if ((threadIdx.x & 31) == 0) red[wid] = v;
    __syncthreads();
    float r = red[0];
    #pragma unroll
    for (int w = 1; w < 8; w++) r = do_max ? fmaxf(r, red[w]) : (r + red[w]);
    return r;
}

__global__ __launch_bounds__(256)
void softmax_kernel()
{
    const size_t rowoff = (size_t)blockIdx.x * HWSZ;
    const float* p = g_energy + rowoff;
    __half* q = g_Ph + rowoff;
    const int tid = threadIdx.x;

    float2 v0 = *reinterpret_cast<const float2*>(&p[tid * 2]);
    float2 v1 = *reinterpret_cast<const float2*>(&p[512 + tid * 2]);
    float mx = fmaxf(fmaxf(v0.x, v0.y), fmaxf(v1.x, v1.y));
    mx = block_reduce(mx, true);
    __syncthreads();

    v0.x = __expf(v0.x - mx); v0.y = __expf(v0.y - mx);
    v1.x = __expf(v1.x - mx); v1.y = __expf(v1.y - mx);
    const float s = block_reduce(v0.x + v0.y + v1.x + v1.y, false);

    *reinterpret_cast<__half2*>(&q[tid * 2])       = __floats2half2_rn(v0.x, v0.y);
    *reinterpret_cast<__half2*>(&q[512 + tid * 2]) = __floats2half2_rn(v1.x, v1.y);
    if (tid == 0) g_inv[blockIdx.x] = 1.0f / s;
}

// ---------------------------------------------------------------------------
// attended: D[c][n] = sum_m fvalh[c][m] * P[n][m];
// out[c][n] = x[c][n] + param * inv[n] * D[c][n]
// ---------------------------------------------------------------------------
__global__ __launch_bounds__(256, 3)
void attended_kernel(const float* __restrict__ x,
                     const float* __restrict__ param,
                     float* __restrict__ out)
{
    const int b  = blockIdx.z;
    const int c0 = blockIdx.x * 128;
    const int n0 = blockIdx.y * 64;
    const int tid = threadIdx.x;
    const int wid = tid >> 5, lane = tid & 31;
    const int wm = (wid >> 1) * 32, wn = (wid & 1) * 32;
    const int g = lane >> 2, tig = lane & 3;

    float acc[2][4][4] = {};
    gemm_tn(g_fvalh + ((size_t)b * CCH + c0) * HWSZ, HWSZ,
            g_Ph + ((size_t)b * HWSZ + n0) * HWSZ, HWSZ,
            HWSZ / 64, acc, wm, wn);

    const float ps = param[0];
    const float* xb = x   + (size_t)b * CCH * HWSZ;
    float*       ob = out + (size_t)b * CCH * HWSZ;
    #pragma unroll
    for (int ni = 0; ni < 4; ni++) {
        const int col = n0 + wn + ni * 8 + tig * 2;
        float2 iv = *reinterpret_cast<const float2*>(&g_inv[(size_t)b * HWSZ + col]);
        const float sx = ps * iv.x, sy = ps * iv.y;
        #pragma unroll
        for (int mi = 0; mi < 2; mi++) {
            const int row = c0 + wm + mi * 16 + g;
            {
                const size_t off = (size_t)row * HWSZ + col;
                float2 xv = *reinterpret_cast<const float2*>(&xb[off]);
                *reinterpret_cast<float2*>(&ob[off]) =
                    make_float2(xv.x + sx * acc[mi][ni][0],
                                xv.y + sy * acc[mi][ni][1]);
            }
            {
                const size_t off = (size_t)(row + 8) * HWSZ + col;
                float2 xv = *reinterpret_cast<const float2*>(&xb[off]);
                *reinterpret_cast<float2*>(&ob[off]) =
                    make_float2(xv.x + sx * acc[mi][ni][2],
                                xv.y + sy * acc[mi][ni][3]);
            }
        }
    }
}

// ---------------------------------------------------------------------------
extern "C" void kernel_launch(void* const* d_in, const int* in_sizes, int n_in,
                              void* d_out, int out_size)
{
    const float* x     = (const float*)d_in[0];
    const float* Wk    = (const float*)d_in[1];
    const float* bk    = (const float*)d_in[2];
    const float* Wp    = (const float*)d_in[3];
    const float* bp    = (const float*)d_in[4];
    const float* Wv    = (const float*)d_in[5];
    const float* bv    = (const float*)d_in[6];
    const float* param = (const float*)d_in[7];
    float* out = (float*)d_out;

    const int DSM = 2 * STAGE_BYTES;   // 48 KB dynamic smem
    cudaFuncSetAttribute(proj_kp_kernel,  cudaFuncAttributeMaxDynamicSharedMemorySize, DSM);
    cudaFuncSetAttribute(proj_v_kernel,   cudaFuncAttributeMaxDynamicSharedMemorySize, DSM);
    cudaFuncSetAttribute(energy_kernel,   cudaFuncAttributeMaxDynamicSharedMemorySize, DSM);
    cudaFuncSetAttribute(attended_kernel, cudaFuncAttributeMaxDynamicSharedMemorySize, DSM);

    wconv_kernel    <<<dim3((2 * RCH + CCH) * CCH / 256), 256>>>(Wk, Wp, Wv);
    transpose_kernel<<<dim3(HWSZ / 32, CCH / 32, BATCH), 256>>>(x);

    proj_kp_kernel<<<dim3(HWSZ / 128, 8, BATCH), 256, DSM>>>(bk, bp);
    proj_v_kernel <<<dim3(CCH / 128, HWSZ / 64, BATCH), 256, DSM>>>(bv);

    energy_kernel <<<dim3(HWSZ / 64, HWSZ / 128, BATCH), 256, DSM>>>();
    softmax_kernel<<<dim3(BATCH * HWSZ), 256>>>();

    attended_kernel<<<dim3(CCH / 128, HWSZ / 64, BATCH), 256, DSM>>>(x, param, out);
}

// round 17
// speedup vs baseline: 1.1735x; 1.1735x over previous
#include <cuda_runtime.h>
#include <cuda_fp16.h>
#include <cuda_bf16.h>
#include <cstdint>

#define BATCH 32
#define CCH   512
#define RCH   256
#define HWSZ  1024

#define EXP_SHIFT 60.0f

// Scratch (device globals). Projection operands fp16; P and V bf16.
__device__ __half        g_xTh    [BATCH * HWSZ * CCH];           // 32 MB [b][n][c]
__device__ __half        g_Wh     [(RCH + RCH + CCH) * CCH];      // 1 MB  Wk|Wp|Wv
__device__ __half        g_fkeyTh [BATCH * HWSZ * RCH];           // 16 MB [b][n][r]
__device__ __half        g_fprodTh[BATCH * HWSZ * RCH];           // 16 MB [b][m][r]
__device__ __nv_bfloat16 g_fvalb  [BATCH * CCH * HWSZ];           // 32 MB [b][c][m]
__device__ __nv_bfloat16 g_Pb     [(size_t)BATCH * HWSZ * HWSZ]; // 64 MB P=exp(s-60)
__device__ float         g_epart  [BATCH * HWSZ * 8];             // per-mtile row sums
__device__ float         g_inv    [BATCH * HWSZ];                 // 1/rowsum

// ---------------------------------------------------------------------------
// PTX helpers
// ---------------------------------------------------------------------------
__device__ __forceinline__ uint32_t s2u(const void* p) {
    uint32_t a;
    asm("{ .reg .u64 t; cvta.to.shared.u64 t, %1; cvt.u32.u64 %0, t; }" : "=r"(a) : "l"(p));
    return a;
}
__device__ __forceinline__ void cp_async16(uint32_t dst, const void* src) {
    asm volatile("cp.async.cg.shared.global [%0], [%1], 16;" :: "r"(dst), "l"(src));
}
#define CP_COMMIT() asm volatile("cp.async.commit_group;" ::: "memory")
#define CP_WAIT1()  asm volatile("cp.async.wait_group 1;" ::: "memory")
#define CP_WAIT0()  asm volatile("cp.async.wait_group 0;" ::: "memory")

__device__ __forceinline__ void mma_f16(float c[4], const uint32_t a[4], const uint32_t b[2]) {
    asm volatile(
        "mma.sync.aligned.m16n8k16.row.col.f32.f16.f16.f32 "
        "{%0,%1,%2,%3}, {%4,%5,%6,%7}, {%8,%9}, {%0,%1,%2,%3};"
        : "+f"(c[0]), "+f"(c[1]), "+f"(c[2]), "+f"(c[3])
        : "r"(a[0]), "r"(a[1]), "r"(a[2]), "r"(a[3]), "r"(b[0]), "r"(b[1]));
}
__device__ __forceinline__ void mma_bf16(float c[4], const uint32_t a[4], const uint32_t b[2]) {
    asm volatile(
        "mma.sync.aligned.m16n8k16.row.col.f32.bf16.bf16.f32 "
        "{%0,%1,%2,%3}, {%4,%5,%6,%7}, {%8,%9}, {%0,%1,%2,%3};"
        : "+f"(c[0]), "+f"(c[1]), "+f"(c[2]), "+f"(c[3])
        : "r"(a[0]), "r"(a[1]), "r"(a[2]), "r"(a[3]), "r"(b[0]), "r"(b[1]));
}

__device__ __forceinline__ void ldsm4(uint32_t* r, uint32_t addr) {
    asm volatile("ldmatrix.sync.aligned.m8n8.x4.shared.b16 {%0,%1,%2,%3}, [%4];"
        : "=r"(r[0]), "=r"(r[1]), "=r"(r[2]), "=r"(r[3]) : "r"(addr));
}

// ---------------------------------------------------------------------------
// GEMM core (R13 config): D[128x128]fp32 = A[128xK] * B[128xK]^T, 16-bit
// k-minor operands, BK=64 elements (128B rows), 2-stage cp.async pipeline,
// XOR-swizzled tiles, ldmatrix fragments. 8 warps 2(m)x4(n), warp tile 64x32.
// ---------------------------------------------------------------------------
#define TILE_WORDS (128 * 32)            // 16 KB per tile
#define STAGE_WORDS (2 * TILE_WORDS)

extern __shared__ uint32_t smp[];

__device__ __forceinline__ void stage_tile(uint32_t sbase, const __half* src,
                                           size_t ld, int tid)
{
    #pragma unroll
    for (int v = 0; v < 4; v++) {
        const int idx = tid + v * 256;
        const int row = idx >> 3;
        const int cg  = idx & 7;                         // 16B group = 8 elems
        const uint32_t col4 = (cg * 4) ^ ((row & 7) * 4);
        cp_async16(sbase + (row * 32 + col4) * 4, src + (size_t)row * ld + cg * 8);
    }
}

struct FragAddr {
    uint32_t afull[4], aK0[4];
    uint32_t bfull[2], bK0[2];
};

__device__ __forceinline__ FragAddr make_frag_addr(int lane, int wm, int wn)
{
    FragAddr f;
    const int rowoff = ((lane >> 3) & 1) * 8 + (lane & 7);
    const int c4a = ((lane >> 4) & 1) * 4;
    #pragma unroll
    for (int mi = 0; mi < 4; mi++) {
        const int arow = wm + mi * 16 + rowoff;
        f.afull[mi] = (uint32_t)arow * 128;
        f.aK0[mi]   = (uint32_t)(c4a ^ (4 * (arow & 7)));
    }
    const int c4b = ((lane >> 3) & 1) * 4;
    #pragma unroll
    for (int p = 0; p < 2; p++) {
        const int brow = wn + (2 * p + ((lane >> 4) & 1)) * 8 + (lane & 7);
        f.bfull[p] = (uint32_t)brow * 128;
        f.bK0[p]   = (uint32_t)(c4b ^ (4 * (brow & 7)));
    }
    return f;
}

template<bool USE_BF16>
__device__ __forceinline__ void mma_chunk(uint32_t abase, uint32_t bbase,
                                          const FragAddr& f, float acc[4][4][4])
{
    #pragma unroll
    for (int kk = 0; kk < 4; kk++) {                 // 4 k16-steps per BK=64
        const uint32_t k = kk * 8;                   // word offset (32B/step)
        uint32_t a[4][4], b[2][4];
        #pragma unroll
        for (int mi = 0; mi < 4; mi++)
            ldsm4(a[mi], abase + f.afull[mi] + ((k ^ f.aK0[mi]) << 2));
        #pragma unroll
        for (int p = 0; p < 2; p++)
            ldsm4(b[p], bbase + f.bfull[p] + ((k ^ f.bK0[p]) << 2));
        #pragma unroll
        for (int mi = 0; mi < 4; mi++)
            #pragma unroll
            for (int ni = 0; ni < 4; ni++) {
                if (USE_BF16) mma_bf16(acc[mi][ni], a[mi], &b[ni >> 1][(ni & 1) * 2]);
                else          mma_f16 (acc[mi][ni], a[mi], &b[ni >> 1][(ni & 1) * 2]);
            }
    }
}

template<bool USE_BF16>
__device__ __forceinline__ void gemm_tn(const __half* __restrict__ A, size_t lda,
                                        const __half* __restrict__ B, size_t ldb,
                                        int nIter, float acc[4][4][4],
                                        int wm, int wn)
{
    const int tid = threadIdx.x;
    const uint32_t sm0 = s2u(smp);
    const FragAddr f = make_frag_addr(tid & 31, wm, wn);

    stage_tile(sm0, A, lda, tid);
    stage_tile(sm0 + TILE_WORDS * 4, B, ldb, tid);
    CP_COMMIT();

    for (int it = 0; it < nIter; ++it) {
        if (it + 1 < nIter) {
            const uint32_t sb = sm0 + ((it + 1) & 1) * (STAGE_WORDS * 4);
            stage_tile(sb, A + (size_t)(it + 1) * 64, lda, tid);
            stage_tile(sb + TILE_WORDS * 4, B + (size_t)(it + 1) * 64, ldb, tid);
            CP_COMMIT();
            CP_WAIT1();
        } else {
            CP_WAIT0();
        }
        __syncthreads();
        const uint32_t abase = sm0 + (it & 1) * (STAGE_WORDS * 4);
        mma_chunk<USE_BF16>(abase, abase + TILE_WORDS * 4, f, acc);
        __syncthreads();
    }
}

// ---------------------------------------------------------------------------
// W -> half converter (Wk | Wp | Wv packed into g_Wh)
// ---------------------------------------------------------------------------
__global__ __launch_bounds__(256)
void wconv_kernel(const float* __restrict__ Wk, const float* __restrict__ Wp,
                  const float* __restrict__ Wv)
{
    const int i = blockIdx.x * 256 + threadIdx.x;
    float v;
    if (i < RCH * CCH)          v = Wk[i];
    else if (i < 2 * RCH * CCH) v = Wp[i - RCH * CCH];
    else                        v = Wv[i - 2 * RCH * CCH];
    g_Wh[i] = __float2half(v);
}

// ---------------------------------------------------------------------------
// Transpose + convert: xTh[b][n][c] = half(x[b][c][n])
// ---------------------------------------------------------------------------
__global__ __launch_bounds__(256)
void transpose_kernel(const float* __restrict__ x)
{
    __shared__ float t[32][33];
    const int b  = blockIdx.z;
    const int n0 = blockIdx.x * 32;
    const int c0 = blockIdx.y * 32;
    const int tx = threadIdx.x & 31;
    const int ty = threadIdx.x >> 5;

    const float* xb = x + (size_t)b * CCH * HWSZ;
    #pragma unroll
    for (int i = 0; i < 4; i++)
        t[ty + i * 8][tx] = xb[(size_t)(c0 + ty + i * 8) * HWSZ + n0 + tx];
    __syncthreads();
    __half* xT = g_xTh + (size_t)b * HWSZ * CCH;
    #pragma unroll
    for (int i = 0; i < 4; i++)
        xT[(size_t)(n0 + ty + i * 8) * CCH + c0 + tx] = __float2half(t[tx][ty + i * 8]);
}

// ---------------------------------------------------------------------------
// proj_kp (merged k+p): D[n][r] = sum_c xTh[n][c] * Wh[r][c] + bias[r] -> fp16
// ---------------------------------------------------------------------------
__global__ __launch_bounds__(256)
void proj_kp_kernel(const float* __restrict__ bk, const float* __restrict__ bp)
{
    const int b  = blockIdx.z;
    const int n0 = blockIdx.x * 128;
    const int which = blockIdx.y >> 1;
    const int r0 = (blockIdx.y & 1) * 128;
    const __half* W    = g_Wh + which * (RCH * CCH);
    const float*  bias = which ? bp : bk;
    __half* dst        = which ? g_fprodTh : g_fkeyTh;

    const int tid = threadIdx.x;
    const int wid = tid >> 5, lane = tid & 31;
    const int wm = (wid >> 2) * 64, wn = (wid & 3) * 32;
    const int g = lane >> 2, tig = lane & 3;

    float acc[4][4][4] = {};
    gemm_tn<false>(g_xTh + (size_t)b * HWSZ * CCH + (size_t)n0 * CCH, CCH,
                   W + (size_t)r0 * CCH, CCH, CCH / 64, acc, wm, wn);

    #pragma unroll
    for (int ni = 0; ni < 4; ni++) {
        const int col = r0 + wn + ni * 8 + tig * 2;
        const float2 bv = *reinterpret_cast<const float2*>(&bias[col]);
        #pragma unroll
        for (int mi = 0; mi < 4; mi++) {
            const int row = n0 + wm + mi * 16 + g;
            *reinterpret_cast<__half2*>(&dst[((size_t)b * HWSZ + row) * RCH + col]) =
                __floats2half2_rn(acc[mi][ni][0] + bv.x, acc[mi][ni][1] + bv.y);
            *reinterpret_cast<__half2*>(&dst[((size_t)b * HWSZ + row + 8) * RCH + col]) =
                __floats2half2_rn(acc[mi][ni][2] + bv.x, acc[mi][ni][3] + bv.y);
        }
    }
}

// ---------------------------------------------------------------------------
// proj_v: D[c][m] = sum_ci Wvh[c][ci] * xTh[m][ci] + bias[c] -> fvalb (bf16)
// ---------------------------------------------------------------------------
__global__ __launch_bounds__(256)
void proj_v_kernel(const float* __restrict__ bias)
{
    const int b  = blockIdx.z;
    const int c0 = blockIdx.x * 128;
    const int m0 = blockIdx.y * 128;
    const int tid = threadIdx.x;
    const int wid = tid >> 5, lane = tid & 31;
    const int wm = (wid >> 2) * 64, wn = (wid & 3) * 32;
    const int g = lane >> 2, tig = lane & 3;

    float acc[4][4][4] = {};
    gemm_tn<false>(g_Wh + 2 * (RCH * CCH) + (size_t)c0 * CCH, CCH,
                   g_xTh + (size_t)b * HWSZ * CCH + (size_t)m0 * CCH, CCH,
                   CCH / 64, acc, wm, wn);

    #pragma unroll
    for (int mi = 0; mi < 4; mi++) {
        const int row = c0 + wm + mi * 16 + g;
        const float b0 = bias[row], b1 = bias[row + 8];
        #pragma unroll
        for (int ni = 0; ni < 4; ni++) {
            const int col = m0 + wn + ni * 8 + tig * 2;
            *reinterpret_cast<__nv_bfloat162*>(&g_fvalb[((size_t)b * CCH + row) * HWSZ + col]) =
                __floats2bfloat162_rn(acc[mi][ni][0] + b0, acc[mi][ni][1] + b0);
            *reinterpret_cast<__nv_bfloat162*>(&g_fvalb[((size_t)b * CCH + row + 8) * HWSZ + col]) =
                __floats2bfloat162_rn(acc[mi][ni][2] + b1, acc[mi][ni][3] + b1);
        }
    }
}

// ---------------------------------------------------------------------------
// energy: s = fkeyT . fprodT; writes P = bf16(exp(s-60)) and per-CTA row
// partial sums (computed from the bf16-rounded values for consistency).
// ---------------------------------------------------------------------------
__global__ __launch_bounds__(256)
void energy_kernel()
{
    const int b  = blockIdx.z;
    const int m0 = blockIdx.x * 128;
    const int n0 = blockIdx.y * 128;
    const int tid = threadIdx.x;
    const int wid = tid >> 5, lane = tid & 31;
    const int wm = (wid >> 2) * 64, wn = (wid & 3) * 32;
    const int g = lane >> 2, tig = lane & 3;

    float acc[4][4][4] = {};
    gemm_tn<false>(g_fkeyTh  + ((size_t)b * HWSZ + n0) * RCH, RCH,
                   g_fprodTh + ((size_t)b * HWSZ + m0) * RCH, RCH,
                   RCH / 64, acc, wm, wn);

    // exp, bf16-round (keep rounded values for the sums), store P tile
    __nv_bfloat16* Pb = g_Pb + (size_t)b * HWSZ * HWSZ;
    float rowsum[4][2] = {};                         // [mi][lo/hi]
    #pragma unroll
    for (int mi = 0; mi < 4; mi++) {
        const int row = n0 + wm + mi * 16 + g;
        #pragma unroll
        for (int ni = 0; ni < 4; ni++) {
            const int col = m0 + wn + ni * 8 + tig * 2;
            __nv_bfloat162 p01 = __floats2bfloat162_rn(
                __expf(acc[mi][ni][0] - EXP_SHIFT), __expf(acc[mi][ni][1] - EXP_SHIFT));
            __nv_bfloat162 p23 = __floats2bfloat162_rn(
                __expf(acc[mi][ni][2] - EXP_SHIFT), __expf(acc[mi][ni][3] - EXP_SHIFT));
            *reinterpret_cast<__nv_bfloat162*>(&Pb[(size_t)row * HWSZ + col]) = p01;
            *reinterpret_cast<__nv_bfloat162*>(&Pb[(size_t)(row + 8) * HWSZ + col]) = p23;
            rowsum[mi][0] += __bfloat162float(p01.x) + __bfloat162float(p01.y);
            rowsum[mi][1] += __bfloat162float(p23.x) + __bfloat162float(p23.y);
        }
    }

    // per-row partial sums over this CTA's 128 m-columns (pipeline smem dead)
    float* spart = reinterpret_cast<float*>(smp);    // [128][5]
    #pragma unroll
    for (int mi = 0; mi < 4; mi++) {
        float slo = rowsum[mi][0], shi = rowsum[mi][1];
        #pragma unroll
        for (int o = 1; o < 4; o <<= 1) {
            slo += __shfl_xor_sync(0xffffffffu, slo, o);
            shi += __shfl_xor_sync(0xffffffffu, shi, o);
        }
        if (tig == 0) {
            spart[(wm + mi * 16 + g) * 5 + (wid & 3)] = slo;
            spart[(wm + mi * 16 + g + 8) * 5 + (wid & 3)] = shi;
        }
    }
    __syncthreads();
    if (tid < 128) {
        const float s = spart[tid * 5 + 0] + spart[tid * 5 + 1] +
                        spart[tid * 5 + 2] + spart[tid * 5 + 3];
        g_epart[((size_t)b * HWSZ + n0 + tid) * 8 + blockIdx.x] = s;
    }
}

// ---------------------------------------------------------------------------
// inv: g_inv[row] = 1 / sum_8 partials
// ---------------------------------------------------------------------------
__global__ __launch_bounds__(1024)
void inv_kernel()
{
    const int row = blockIdx.x * 1024 + threadIdx.x;
    const float* p = &g_epart[(size_t)row * 8];
    float s = 0.f;
    #pragma unroll
    for (int i = 0; i < 8; i++) s += p[i];
    g_inv[row] = 1.0f / s;
}

// ---------------------------------------------------------------------------
// attended (bf16): D[c][n] = sum_m fvalb[c][m] * P[n][m];
// out[c][n] = x[c][n] + param * inv[n] * D[c][n]
// ---------------------------------------------------------------------------
__global__ __launch_bounds__(256)
void attended_kernel(const float* __restrict__ x,
                     const float* __restrict__ param,
                     float* __restrict__ out)
{
    const int b  = blockIdx.z;
    const int c0 = blockIdx.x * 128;
    const int n0 = blockIdx.y * 128;
    const int tid = threadIdx.x;
    const int wid = tid >> 5, lane = tid & 31;
    const int wm = (wid >> 2) * 64, wn = (wid & 3) * 32;
    const int g = lane >> 2, tig = lane & 3;

    float acc[4][4][4] = {};
    gemm_tn<true>(
        reinterpret_cast<const __half*>(g_fvalb + ((size_t)b * CCH + c0) * HWSZ), HWSZ,
        reinterpret_cast<const __half*>(g_Pb + ((size_t)b * HWSZ + n0) * HWSZ), HWSZ,
        HWSZ / 64, acc, wm, wn);

    const float ps = param[0];
    const float* xb = x   + (size_t)b * CCH * HWSZ;
    float*       ob = out + (size_t)b * CCH * HWSZ;
    #pragma unroll
    for (int ni = 0; ni < 4; ni++) {
        const int col = n0 + wn + ni * 8 + tig * 2;
        float2 iv = *reinterpret_cast<const float2*>(&g_inv[(size_t)b * HWSZ + col]);
        const float sx = ps * iv.x, sy = ps * iv.y;
        #pragma unroll
        for (int mi = 0; mi < 4; mi++) {
            const int row = c0 + wm + mi * 16 + g;
            {
                const size_t off = (size_t)row * HWSZ + col;
                float2 xv = *reinterpret_cast<const float2*>(&xb[off]);
                *reinterpret_cast<float2*>(&ob[off]) =
                    make_float2(xv.x + sx * acc[mi][ni][0],
                                xv.y + sy * acc[mi][ni][1]);
            }
            {
                const size_t off = (size_t)(row + 8) * HWSZ + col;
                float2 xv = *reinterpret_cast<const float2*>(&xb[off]);
                *reinterpret_cast<float2*>(&ob[off]) =
                    make_float2(xv.x + sx * acc[mi][ni][2],
                                xv.y + sy * acc[mi][ni][3]);
            }
        }
    }
}

// ---------------------------------------------------------------------------
extern "C" void kernel_launch(void* const* d_in, const int* in_sizes, int n_in,
                              void* d_out, int out_size)
{
    const float* x     = (const float*)d_in[0];
    const float* Wk    = (const float*)d_in[1];
    const float* bk    = (const float*)d_in[2];
    const float* Wp    = (const float*)d_in[3];
    const float* bp    = (const float*)d_in[4];
    const float* Wv    = (const float*)d_in[5];
    const float* bv    = (const float*)d_in[6];
    const float* param = (const float*)d_in[7];
    float* out = (float*)d_out;

    const int DSM = 2 * STAGE_WORDS * 4;   // 64 KB dynamic smem
    cudaFuncSetAttribute(proj_kp_kernel,  cudaFuncAttributeMaxDynamicSharedMemorySize, DSM);
    cudaFuncSetAttribute(proj_v_kernel,   cudaFuncAttributeMaxDynamicSharedMemorySize, DSM);
    cudaFuncSetAttribute(energy_kernel,   cudaFuncAttributeMaxDynamicSharedMemorySize, DSM);
    cudaFuncSetAttribute(attended_kernel, cudaFuncAttributeMaxDynamicSharedMemorySize, DSM);

    wconv_kernel    <<<dim3((2 * RCH + CCH) * CCH / 256), 256>>>(Wk, Wp, Wv);
    transpose_kernel<<<dim3(HWSZ / 32, CCH / 32, BATCH), 256>>>(x);

    proj_kp_kernel<<<dim3(HWSZ / 128, 4, BATCH), 256, DSM>>>(bk, bp);
    proj_v_kernel <<<dim3(CCH / 128, HWSZ / 128, BATCH), 256, DSM>>>(bv);

    energy_kernel<<<dim3(HWSZ / 128, HWSZ / 128, BATCH), 256, DSM>>>();
    inv_kernel   <<<dim3(BATCH * HWSZ / 1024), 1024>>>();

    attended_kernel<<<dim3(CCH / 128, HWSZ / 128, BATCH), 256, DSM>>>(x, param, out);
}